// round 9
// baseline (speedup 1.0000x reference)
#include <cuda_runtime.h>

// Problem constants (fixed by dataset: B=16, H=1024, W=2048, G=8, C=19)
#define NB      524288          // number of 8x8 label blocks = 16*128*256
#define NC      19
#define WID     2048
#define HEI     1024
#define GS      8
#define WB      (WID/GS)        // 256
#define HB      (HEI/GS)        // 128
#define NCTAS   (NB/256)        // 2048 CTAs, 8 warps/CTA, 32 blocks/warp
#define F_PER_WARP (32*NC)      // 608 floats = 152 float4 exactly
#define V_PER_WARP (F_PER_WARP/4)  // 152 = 4*32 + 24

// Allocation-free scratch (__device__ globals per harness rules)
__device__ double       g_partials[NCTAS];
__device__ unsigned int g_count = 0;           // self-resetting completion counter

// Numerically stable softplus: max(x,0) + log(1 + exp(-|x|))
__device__ __forceinline__ float softplus_f(float x)
{
    float e = __expf(-fabsf(x));
    return fmaxf(x, 0.0f) + __logf(1.0f + e);
}

// ---------------------------------------------------------------------------
// Warp-autonomous fused kernel: each warp builds masks for its 32 blocks,
// syncs only within the warp (smem strip), then makes a SINGLE pass over its
// 608-float preds slice computing softplus(x) - t*x. No CTA barrier until
// the final reduction, so warps drift and DRAM demand stays continuous.
// ---------------------------------------------------------------------------
__global__ void __launch_bounds__(256)
fused_kernel(const int*   __restrict__ tgt,
             const float* __restrict__ preds,
             float*       __restrict__ out)
{
    __shared__ unsigned int sm_strip[8][33];   // per-warp masks (+pad entry)
    __shared__ float  ws[8];
    __shared__ double sh[256];

    const unsigned int tid  = threadIdx.x;
    const unsigned int lane = tid & 31u;
    const unsigned int wix  = tid >> 5;                       // warp in CTA
    const unsigned int warp = (blockIdx.x << 3) | wix;        // global warp id

    // ---- Phase A: presence mask for block t = 32*warp + lane ----
    unsigned int t  = (warp << 5) | lane;
    unsigned int bw = t & (WB - 1);
    unsigned int bh = (t >> 8) & (HB - 1);
    unsigned int b  = t >> 15;
    size_t tbase = ((size_t)(b * HEI + bh * GS)) * WID + (size_t)bw * GS;
    const int4* tp = (const int4*)(tgt + tbase);   // 16B aligned

    unsigned int m = 0u;
#pragma unroll
    for (int r = 0; r < 8; r++) {
        int4 v0 = __ldcs(&tp[r * (WID / 4)]);
        int4 v1 = __ldcs(&tp[r * (WID / 4) + 1]);
        m |= (1u << v0.x) | (1u << v0.y) | (1u << v0.z) | (1u << v0.w);
        m |= (1u << v1.x) | (1u << v1.y) | (1u << v1.z) | (1u << v1.w);
    }
    sm_strip[wix][lane] = m;
    if (lane == 0) sm_strip[wix][32] = 0u;
    __syncwarp();

    // ---- Phase B: single pass over this warp's 152 preds float4 ----
    const float4* pv = (const float4*)(preds + (size_t)warp * F_PER_WARP);
    float s = 0.0f;
#pragma unroll
    for (int it = 0; it < 5; it++) {
        unsigned int j = lane + (unsigned int)it * 32u;
        if (it == 4 && lane >= (V_PER_WARP - 128)) break;   // tail: lane < 24
        unsigned int e0 = j * 4u;
        unsigned int q  = e0 / 19u;                  // 0..31 (magic div)
        unsigned int c0 = e0 - q * 19u;              // 0..18
        unsigned int mm = (sm_strip[wix][q] | (sm_strip[wix][q + 1] << 19)) >> c0;

        float4 x = __ldcs(&pv[j]);
        s += softplus_f(x.x) + softplus_f(x.y)
           + softplus_f(x.z) + softplus_f(x.w);
        if (mm & 1u) s -= x.x;
        if (mm & 2u) s -= x.y;
        if (mm & 4u) s -= x.z;
        if (mm & 8u) s -= x.w;
    }

    // ---- CTA reduction -> double partial ----
#pragma unroll
    for (int o = 16; o > 0; o >>= 1)
        s += __shfl_xor_sync(0xffffffffu, s, o);
    if (lane == 0u) ws[wix] = s;
    __syncthreads();
    if (tid < 32u) {
        float v = (tid < 8u) ? ws[tid] : 0.0f;
#pragma unroll
        for (int o = 4; o > 0; o >>= 1)
            v += __shfl_xor_sync(0xffffffffu, v, o);
        if (tid == 0u) {
            g_partials[blockIdx.x] = (double)v;
            __threadfence();
            unsigned int done = atomicAdd(&g_count, 1u);
            ws[0] = (done == (unsigned int)(NCTAS - 1)) ? 1.0f : 0.0f;
        }
    }
    __syncthreads();
    if (ws[0] == 0.0f) return;

    // ---- Last CTA: deterministic final reduction over all partials ----
    double d = 0.0;
    for (unsigned int i = tid; i < (unsigned int)NCTAS; i += 256u)
        d += g_partials[i];
    sh[tid] = d;
    __syncthreads();
#pragma unroll
    for (int o = 128; o > 0; o >>= 1) {
        if (tid < (unsigned int)o) sh[tid] += sh[tid + o];
        __syncthreads();
    }
    if (tid == 0) {
        out[0] = (float)(sh[0] / ((double)NB * (double)NC));
        g_count = 0;                         // reset for next graph replay
    }
}

// ---------------------------------------------------------------------------
extern "C" void kernel_launch(void* const* d_in, const int* in_sizes, int n_in,
                              void* d_out, int out_size)
{
    const float* preds = (const float*)d_in[0];
    const int*   tgt   = (const int*)d_in[1];
    // d_in[2] = grid_size (always 8 for this problem's shapes)

    fused_kernel<<<NCTAS, 256>>>(tgt, preds, (float*)d_out);
}

// round 10
// speedup vs baseline: 1.0017x; 1.0017x over previous
#include <cuda_runtime.h>

// Problem constants (fixed by dataset: B=16, H=1024, W=2048, G=8, C=19)
#define NB      524288          // number of 8x8 label blocks = 16*128*256
#define NC      19
#define WID     2048
#define HEI     1024
#define GS      8
#define HB      (HEI/GS)        // 128 block-rows per image
#define BLOCKS_PER_TILE 256     // one row of label blocks per tile
#define NTILES  (NB/BLOCKS_PER_TILE)           // 2048
#define F_PER_TILE (BLOCKS_PER_TILE*NC)        // 4864 floats
#define V_PER_TILE (F_PER_TILE/4)              // 1216 float4 (= 4*256 + 192)
#define GRID    1216            // 152 SMs * 8 resident CTAs (persistent)

// Allocation-free scratch (__device__ globals per harness rules)
__device__ double       g_partials[NTILES];
__device__ unsigned int g_tile  = 0;           // work-stealing tile counter
__device__ unsigned int g_count = 0;           // CTA completion counter

// Numerically stable softplus: max(x,0) + log(1 + exp(-|x|))
__device__ __forceinline__ float softplus_f(float x)
{
    float e = __expf(-fabsf(x));
    return fmaxf(x, 0.0f) + __logf(1.0f + e);
}

// ---------------------------------------------------------------------------
// Persistent fused kernel with atomic tile scheduler.
// Per tile (R7 phase order):
//   1) preds stream + softplus accumulate
//   2) targets stream, DENSE pattern: warp reads 512B contiguous per row;
//      lane l covers (block l/2, half l&1); pair-merge masks via shfl_xor.
//   3) barrier; correction pass re-reads preds (L1/L2 hits)
//   4) fixed-tree per-tile partial -> g_partials[tile]   (deterministic)
// Last CTA sums all tile partials in fixed order.
// ---------------------------------------------------------------------------
__global__ void __launch_bounds__(256)
fused_kernel(const int*   __restrict__ tgt,
             const float* __restrict__ preds,
             float*       __restrict__ out)
{
    __shared__ unsigned int sm_mask[BLOCKS_PER_TILE + 1];
    __shared__ unsigned int sm_tile;
    __shared__ float  ws[8];
    __shared__ double sh[256];

    const unsigned int tid  = threadIdx.x;
    const unsigned int lane = tid & 31u;
    const unsigned int wix  = tid >> 5;        // warp index in CTA (0..7)

    for (;;) {
        if (tid == 0) sm_tile = atomicAdd(&g_tile, 1u);
        __syncthreads();                        // broadcast tile; guard sm_mask reuse
        const unsigned int tile = sm_tile;
        if (tile >= NTILES) break;

        // ---- Phase 1: preds stream + softplus accumulate ----
        const float4* pv = (const float4*)(preds + (size_t)tile * F_PER_TILE);
        float s = 0.0f;
#pragma unroll
        for (int it = 0; it < 5; it++) {
            unsigned int j = tid + (unsigned int)it * 256u;
            if (it == 4 && tid >= (V_PER_TILE - 1024)) break;   // tail: tid<192
            float4 x = pv[j];                                   // keep in L1
            s += softplus_f(x.x) + softplus_f(x.y)
               + softplus_f(x.z) + softplus_f(x.w);
        }

        // ---- Phase 2: targets stream, dense 512B/warp-row pattern ----
        {
            unsigned int bh = tile & (HB - 1);       // 0..127
            unsigned int b  = tile >> 7;             // 0..15
            size_t rowbase = ((size_t)(b * HEI + bh * GS)) * WID;
#pragma unroll
            for (int p = 0; p < 2; p++) {
                // this pass covers blocks [wix*32 + p*16, +16)
                unsigned int blk0 = wix * 32u + (unsigned int)p * 16u;
                const int4* tp = (const int4*)(tgt + rowbase)
                               + (size_t)blk0 * 2 + lane;   // lane-dense 16B
                unsigned int m = 0u;
#pragma unroll
                for (int r = 0; r < 8; r++) {
                    int4 v = __ldcs(&tp[r * (WID / 4)]);
                    m |= (1u << v.x) | (1u << v.y) | (1u << v.z) | (1u << v.w);
                }
                m |= __shfl_xor_sync(0xffffffffu, m, 1);     // merge block halves
                if ((lane & 1u) == 0u)
                    sm_mask[blk0 + (lane >> 1)] = m;
            }
            if (tid == 0) sm_mask[BLOCKS_PER_TILE] = 0u;
        }
        __syncthreads();

        // ---- Phase 3: correction pass; preds reloads hit L1/L2 ----
#pragma unroll
        for (int it = 0; it < 5; it++) {
            unsigned int j = tid + (unsigned int)it * 256u;
            if (it == 4 && tid >= (V_PER_TILE - 1024)) break;
            unsigned int e0 = j * 4u;
            unsigned int q  = e0 / 19u;                  // magic div (const 19)
            unsigned int c0 = e0 - q * 19u;              // 0..18
            unsigned int m0 = sm_mask[q];
            unsigned int m1 = sm_mask[q + 1];
            unsigned int mm = (m0 | (m1 << 19)) >> c0;
            // fake dependency (m0>>24 == 0 always): blocks hoist above barrier
            float4 x = pv[j + (m0 >> 24)];
            if (mm & 1u) s -= x.x;
            if (mm & 2u) s -= x.y;
            if (mm & 4u) s -= x.z;
            if (mm & 8u) s -= x.w;
        }

        // ---- Per-tile fixed-tree reduction -> double partial ----
#pragma unroll
        for (int o = 16; o > 0; o >>= 1)
            s += __shfl_xor_sync(0xffffffffu, s, o);
        if (lane == 0u) ws[wix] = s;
        __syncthreads();
        if (tid < 32u) {
            float v = (tid < 8u) ? ws[tid] : 0.0f;
#pragma unroll
            for (int o = 4; o > 0; o >>= 1)
                v += __shfl_xor_sync(0xffffffffu, v, o);
            if (tid == 0u)
                g_partials[tile] = (double)v;
        }
        __syncthreads();                         // ws/sm_mask safe for next tile
    }

    // ---- Completion protocol: last CTA does the final reduction ----
    if (tid == 0) {
        __threadfence();
        unsigned int done = atomicAdd(&g_count, 1u);
        ws[0] = (done == (unsigned int)(GRID - 1)) ? 1.0f : 0.0f;
    }
    __syncthreads();
    if (ws[0] == 0.0f) return;

    double d = 0.0;
    for (unsigned int i = tid; i < (unsigned int)NTILES; i += 256u)
        d += g_partials[i];
    sh[tid] = d;
    __syncthreads();
#pragma unroll
    for (int o = 128; o > 0; o >>= 1) {
        if (tid < (unsigned int)o) sh[tid] += sh[tid + o];
        __syncthreads();
    }
    if (tid == 0) {
        out[0] = (float)(sh[0] / ((double)NB * (double)NC));
        g_tile  = 0;                        // reset for next graph replay
        g_count = 0;
    }
}

// ---------------------------------------------------------------------------
extern "C" void kernel_launch(void* const* d_in, const int* in_sizes, int n_in,
                              void* d_out, int out_size)
{
    const float* preds = (const float*)d_in[0];
    const int*   tgt   = (const int*)d_in[1];
    // d_in[2] = grid_size (always 8 for this problem's shapes)

    fused_kernel<<<GRID, 256>>>(tgt, preds, (float*)d_out);
}